// round 4
// baseline (speedup 1.0000x reference)
#include <cuda_runtime.h>
#include <math.h>
#include <stdint.h>

#define NB    8
#define NPTS  4096
#define BN    32768
#define NEDGE 524288
#define C0    64
#define C1    128
#define C2    512

// ---------------- scratch ----------------
__device__ float g_h0[BN * C0];
__device__ float g_agg0[BN * C0];
__device__ float g_h1[BN * C1];
__device__ float g_agg1[BN * C1];
__device__ float g_dinv[BN];
__device__ int   g_cnt[BN];
__device__ int   g_rowstart[BN + 1];
__device__ int   g_cur[BN];
__device__ int   g_el[NEDGE];
__device__ float g_lat[NB * C2];
__device__ float g_lat2[NB * C2];
__device__ float g_base[NB * 6];

__device__ __forceinline__ float selu_f(float v) {
    const float scale = 1.0507009873554805f;
    const float alpha = 1.6732632423543772f;
    return v > 0.0f ? scale * v : scale * alpha * expm1f(v);
}

__device__ __forceinline__ void atomicMaxF(float* addr, float v) {
    if (v >= 0.0f) atomicMax((int*)addr, __float_as_int(v));
    else           atomicMin((unsigned int*)addr, __float_as_uint(v));
}

__device__ __forceinline__ uint32_t f2tf32(float v) {
    uint32_t r;
    asm("cvt.rna.tf32.f32 %0, %1;" : "=r"(r) : "f"(v));
    return r;
}

__device__ __forceinline__ void mma_tf32(float d[4],
                                         uint32_t a0, uint32_t a1, uint32_t a2, uint32_t a3,
                                         uint32_t b0, uint32_t b1) {
    asm volatile("mma.sync.aligned.m16n8k8.row.col.f32.tf32.tf32.f32 "
                 "{%0,%1,%2,%3},{%4,%5,%6,%7},{%8,%9},{%0,%1,%2,%3};"
                 : "+f"(d[0]), "+f"(d[1]), "+f"(d[2]), "+f"(d[3])
                 : "r"(a0), "r"(a1), "r"(a2), "r"(a3), "r"(b0), "r"(b1));
}

// ---------------- init ----------------
__global__ void init_kernel() {
    int i = blockIdx.x * blockDim.x + threadIdx.x;
    if (i < BN) g_cnt[i] = 0;
    if (i < NB * C2) g_lat[i] = __int_as_float(0xff800000);
}
__global__ void cnt_kernel(const int* __restrict__ dst) {
    int e = blockIdx.x * blockDim.x + threadIdx.x;
    if (e < NEDGE) atomicAdd(&g_cnt[dst[e]], 1);
}

// ---------------- single-block scan: rowstart/cursor/dinv ----------------
__global__ void __launch_bounds__(1024) scan_kernel() {
    __shared__ int ssum[1024];
    int t = threadIdx.x;
    int base = t << 5;
    int local[32];
    int s = 0;
    #pragma unroll
    for (int j = 0; j < 32; j++) { local[j] = g_cnt[base + j]; s += local[j]; }
    ssum[t] = s;
    __syncthreads();
    for (int off = 1; off < 1024; off <<= 1) {
        int v = (t >= off) ? ssum[t - off] : 0;
        __syncthreads();
        ssum[t] += v;
        __syncthreads();
    }
    int run = ssum[t] - s;   // exclusive base
    #pragma unroll
    for (int j = 0; j < 32; j++) {
        g_rowstart[base + j] = run;
        g_cur[base + j] = run;
        g_dinv[base + j] = rsqrtf((float)(local[j] + 1));
        run += local[j];
    }
    if (t == 1023) g_rowstart[BN] = run;
}

// ---------------- CSR fill: edge list sorted by dst ----------------
__global__ void fill_kernel(const int* __restrict__ src, const int* __restrict__ dst) {
    int e = blockIdx.x * blockDim.x + threadIdx.x;
    if (e >= NEDGE) return;
    int d = dst[e];
    int pos = atomicAdd(&g_cur[d], 1);
    g_el[pos] = src[e];
}

// ---------------- cov + 12->64 + selu -> hs0 ----------------
// 128 threads, 64 points per block.
__global__ void __launch_bounds__(128)
cov_e1_kernel(const float* __restrict__ x,
              const float* __restrict__ w_e1,
              const float* __restrict__ b_e1) {
    __shared__ float xw[88][3];
    __shared__ float ws[12 * 64];
    __shared__ float bs[64];
    __shared__ float feat_s[64][13];
    __shared__ float out_s[64][68];
    int t = threadIdx.x;
    int blk = blockIdx.x;
    int b = blk >> 6;                 // 64 blocks per batch
    int n_base = (blk & 63) << 6;     // batch-local start
    int point0 = blk << 6;

    for (int i = t; i < 88; i += 128) {
        int idx = n_base + i - 12;
        idx = min(max(idx, 0), NPTS - 1);
        const float* xp = x + (((size_t)b << 12) + idx) * 3;
        xw[i][0] = xp[0]; xw[i][1] = xp[1]; xw[i][2] = xp[2];
    }
    for (int i = t; i < 12 * 64; i += 128) ws[i] = w_e1[i];
    if (t < 64) bs[t] = b_e1[t];
    __syncthreads();

    if (t < 64) {
        int n = n_base + t;
        float m0 = 0.f, m1 = 0.f, m2 = 0.f, cnt = 0.f;
        #pragma unroll
        for (int w = 0; w < 25; w++) {
            int nn = n + w - 12;
            if (nn >= 0 && nn < NPTS) {
                m0 += xw[t + w][0]; m1 += xw[t + w][1]; m2 += xw[t + w][2];
                cnt += 1.0f;
            }
        }
        float ic = 1.0f / cnt;
        m0 *= ic; m1 *= ic; m2 *= ic;
        float c00=0,c01=0,c02=0,c11=0,c12=0,c22=0;
        #pragma unroll
        for (int w = 0; w < 25; w++) {
            int nn = n + w - 12;
            if (nn >= 0 && nn < NPTS) {
                float d0 = xw[t + w][0] - m0;
                float d1 = xw[t + w][1] - m1;
                float d2 = xw[t + w][2] - m2;
                c00 = fmaf(d0,d0,c00); c01 = fmaf(d0,d1,c01); c02 = fmaf(d0,d2,c02);
                c11 = fmaf(d1,d1,c11); c12 = fmaf(d1,d2,c12); c22 = fmaf(d2,d2,c22);
            }
        }
        const float s = 1.0f / 23.0f;
        feat_s[t][0] = xw[t + 12][0]; feat_s[t][1] = xw[t + 12][1]; feat_s[t][2] = xw[t + 12][2];
        feat_s[t][3] = c00 * s; feat_s[t][4]  = c01 * s; feat_s[t][5]  = c02 * s;
        feat_s[t][6] = c01 * s; feat_s[t][7]  = c11 * s; feat_s[t][8]  = c12 * s;
        feat_s[t][9] = c02 * s; feat_s[t][10] = c12 * s; feat_s[t][11] = c22 * s;
    }
    __syncthreads();

    int pt = t >> 1, half = t & 1;
    float dv = g_dinv[point0 + pt];
    float feat[12];
    #pragma unroll
    for (int k = 0; k < 12; k++) feat[k] = feat_s[pt][k];
    #pragma unroll 4
    for (int jj = 0; jj < 32; jj++) {
        int j = (half << 5) + jj;
        float acc = bs[j];
        #pragma unroll
        for (int k = 0; k < 12; k++) acc = fmaf(feat[k], ws[k * 64 + j], acc);
        out_s[pt][j] = dv * selu_f(acc);
    }
    __syncthreads();

    for (int i = t; i < 1024; i += 128) {   // 64 rows x 16 float4
        int row = i >> 4, q = i & 15;
        float4 v = *reinterpret_cast<const float4*>(&out_s[row][q << 2]);
        *reinterpret_cast<float4*>(g_h0 + (size_t)(point0 + row) * 64 + (q << 2)) = v;
    }
}

// ---------------- CSR gather: agg[n] = hs[n] + sum_{s in nbr(n)} hs[s] ----------------
// W = floats per node. W=128: warp per node. W=64: half-warp per node.
__global__ void __launch_bounds__(256)
gather128_kernel(const float* __restrict__ hs, float* __restrict__ agg) {
    const float4* h4 = reinterpret_cast<const float4*>(hs);
    int warp = threadIdx.x >> 5, lane = threadIdx.x & 31;
    int node = (blockIdx.x << 3) + warp;
    int rs = g_rowstart[node], re = g_rowstart[node + 1];
    float4 acc = h4[((size_t)node << 5) + lane];
    for (int e = rs; e < re; e++) {
        int s = __ldg(g_el + e);
        float4 v = h4[((size_t)s << 5) + lane];
        acc.x += v.x; acc.y += v.y; acc.z += v.z; acc.w += v.w;
    }
    reinterpret_cast<float4*>(agg)[((size_t)node << 5) + lane] = acc;
}

__global__ void __launch_bounds__(256)
gather64_kernel(const float* __restrict__ hs, float* __restrict__ agg) {
    const float4* h4 = reinterpret_cast<const float4*>(hs);
    int t = threadIdx.x;
    int node = (blockIdx.x << 4) + (t >> 4);
    int lane = t & 15;
    int rs = g_rowstart[node], re = g_rowstart[node + 1];
    float4 acc = h4[((size_t)node << 4) + lane];
    for (int e = rs; e < re; e++) {
        int s = __ldg(g_el + e);
        float4 v = h4[((size_t)s << 4) + lane];
        acc.x += v.x; acc.y += v.y; acc.z += v.z; acc.w += v.w;
    }
    reinterpret_cast<float4*>(agg)[((size_t)node << 4) + lane] = acc;
}

// ---------------- 3xTF32 GEMM: out = selu( (dinv[row]*A[row]) @ W + bias ) ----------------
template<int N, int K, bool DO_MAX>
__global__ void __launch_bounds__(256, 2)
gemm_tf32_kernel(const float* __restrict__ A, const float* __restrict__ dinv,
                 const float* __restrict__ Wt, const float* __restrict__ bias,
                 float* __restrict__ O1, float* __restrict__ lat) {
    __shared__ float Ah[128][20];
    __shared__ float Al[128][20];
    __shared__ float Bh[16][72];
    __shared__ float Bl[16][72];

    int tid = threadIdx.x;
    int warp = tid >> 5, lane = tid & 31;
    int wm = warp >> 2, wn = warp & 3;
    int g = lane >> 2, c = lane & 3;
    int row0 = blockIdx.y * 128, col0 = blockIdx.x * 64;

    int ar = tid >> 1;
    float dv = dinv[row0 + ar];
    int bkr = tid >> 4;
    int bn4 = tid & 15;

    float d[4][2][4];
    #pragma unroll
    for (int mt = 0; mt < 4; mt++)
        #pragma unroll
        for (int nt = 0; nt < 2; nt++)
            #pragma unroll
            for (int r = 0; r < 4; r++) d[mt][nt][r] = 0.0f;

    for (int kt = 0; kt < K; kt += 16) {
        #pragma unroll
        for (int i = 0; i < 2; i++) {
            int q = ((tid & 1) << 1) + i;
            float4 av = *reinterpret_cast<const float4*>(A + (size_t)(row0 + ar) * K + kt + (q << 2));
            float vv[4] = {dv * av.x, dv * av.y, dv * av.z, dv * av.w};
            #pragma unroll
            for (int j = 0; j < 4; j++) {
                uint32_t hb = f2tf32(vv[j]);
                float hf = __uint_as_float(hb);
                Ah[ar][(q << 2) + j] = hf;
                Al[ar][(q << 2) + j] = __uint_as_float(f2tf32(vv[j] - hf));
            }
        }
        {
            float4 bv = *reinterpret_cast<const float4*>(Wt + (size_t)(kt + bkr) * N + col0 + (bn4 << 2));
            float vv[4] = {bv.x, bv.y, bv.z, bv.w};
            #pragma unroll
            for (int j = 0; j < 4; j++) {
                uint32_t hb = f2tf32(vv[j]);
                float hf = __uint_as_float(hb);
                Bh[bkr][(bn4 << 2) + j] = hf;
                Bl[bkr][(bn4 << 2) + j] = __uint_as_float(f2tf32(vv[j] - hf));
            }
        }
        __syncthreads();

        #pragma unroll
        for (int ks = 0; ks < 2; ks++) {
            int k0 = ks << 3;
            uint32_t ahi[4][4], alo[4][4];
            #pragma unroll
            for (int mt = 0; mt < 4; mt++) {
                int rm = wm * 64 + mt * 16;
                ahi[mt][0] = __float_as_uint(Ah[rm + g][k0 + c]);
                ahi[mt][1] = __float_as_uint(Ah[rm + g + 8][k0 + c]);
                ahi[mt][2] = __float_as_uint(Ah[rm + g][k0 + c + 4]);
                ahi[mt][3] = __float_as_uint(Ah[rm + g + 8][k0 + c + 4]);
                alo[mt][0] = __float_as_uint(Al[rm + g][k0 + c]);
                alo[mt][1] = __float_as_uint(Al[rm + g + 8][k0 + c]);
                alo[mt][2] = __float_as_uint(Al[rm + g][k0 + c + 4]);
                alo[mt][3] = __float_as_uint(Al[rm + g + 8][k0 + c + 4]);
            }
            uint32_t bhi[2][2], blo[2][2];
            #pragma unroll
            for (int nt = 0; nt < 2; nt++) {
                int nb = wn * 16 + nt * 8;
                bhi[nt][0] = __float_as_uint(Bh[k0 + c][nb + g]);
                bhi[nt][1] = __float_as_uint(Bh[k0 + c + 4][nb + g]);
                blo[nt][0] = __float_as_uint(Bl[k0 + c][nb + g]);
                blo[nt][1] = __float_as_uint(Bl[k0 + c + 4][nb + g]);
            }
            #pragma unroll
            for (int mt = 0; mt < 4; mt++)
                #pragma unroll
                for (int nt = 0; nt < 2; nt++) {
                    mma_tf32(d[mt][nt], ahi[mt][0], ahi[mt][1], ahi[mt][2], ahi[mt][3],
                             bhi[nt][0], bhi[nt][1]);
                    mma_tf32(d[mt][nt], ahi[mt][0], ahi[mt][1], ahi[mt][2], ahi[mt][3],
                             blo[nt][0], blo[nt][1]);
                    mma_tf32(d[mt][nt], alo[mt][0], alo[mt][1], alo[mt][2], alo[mt][3],
                             bhi[nt][0], bhi[nt][1]);
                }
        }
        __syncthreads();
    }

    float bv[2][2];
    #pragma unroll
    for (int nt = 0; nt < 2; nt++) {
        int cc = col0 + wn * 16 + nt * 8 + (c << 1);
        bv[nt][0] = bias[cc];
        bv[nt][1] = bias[cc + 1];
    }

    if (!DO_MAX) {
        #pragma unroll
        for (int mt = 0; mt < 4; mt++) {
            int rbase = row0 + wm * 64 + mt * 16;
            #pragma unroll
            for (int half = 0; half < 2; half++) {
                int r = rbase + g + half * 8;
                float dv2 = dinv[r];
                #pragma unroll
                for (int nt = 0; nt < 2; nt++) {
                    int cc = col0 + wn * 16 + nt * 8 + (c << 1);
                    float2 o;
                    o.x = dv2 * selu_f(d[mt][nt][half * 2 + 0] + bv[nt][0]);
                    o.y = dv2 * selu_f(d[mt][nt][half * 2 + 1] + bv[nt][1]);
                    *reinterpret_cast<float2*>(O1 + (size_t)r * N + cc) = o;
                }
            }
        }
    } else {
        float mv[2][2];
        #pragma unroll
        for (int nt = 0; nt < 2; nt++) { mv[nt][0] = mv[nt][1] = __int_as_float(0xff800000); }
        #pragma unroll
        for (int mt = 0; mt < 4; mt++)
            #pragma unroll
            for (int nt = 0; nt < 2; nt++) {
                mv[nt][0] = fmaxf(mv[nt][0], fmaxf(selu_f(d[mt][nt][0] + bv[nt][0]),
                                                   selu_f(d[mt][nt][2] + bv[nt][0])));
                mv[nt][1] = fmaxf(mv[nt][1], fmaxf(selu_f(d[mt][nt][1] + bv[nt][1]),
                                                   selu_f(d[mt][nt][3] + bv[nt][1])));
            }
        #pragma unroll
        for (int off = 4; off <= 16; off <<= 1)
            #pragma unroll
            for (int nt = 0; nt < 2; nt++) {
                mv[nt][0] = fmaxf(mv[nt][0], __shfl_xor_sync(0xffffffffu, mv[nt][0], off));
                mv[nt][1] = fmaxf(mv[nt][1], __shfl_xor_sync(0xffffffffu, mv[nt][1], off));
            }
        if (lane < 4) {
            int b = row0 >> 12;
            #pragma unroll
            for (int nt = 0; nt < 2; nt++) {
                int cc = col0 + wn * 16 + nt * 8 + (lane << 1);
                atomicMaxF(&lat[b * C2 + cc], mv[nt][0]);
                atomicMaxF(&lat[b * C2 + cc + 1], mv[nt][1]);
            }
        }
    }
}

// ---------------- lat2 = selu(lat @ w_e2 + b_e2) ----------------
__global__ void e2_kernel(const float* __restrict__ lat, const float* __restrict__ w,
                          const float* __restrict__ bias, float* __restrict__ lat2) {
    __shared__ float row[C2];
    int c = threadIdx.x;
    row[c] = lat[blockIdx.x * C2 + c];
    __syncthreads();
    float acc = bias[c];
    #pragma unroll 8
    for (int k = 0; k < C2; k++) acc = fmaf(row[k], w[k * C2 + c], acc);
    lat2[blockIdx.x * C2 + c] = selu_f(acc);
}

// ---------------- decoder ----------------
__global__ void base_kernel(const float* __restrict__ lat2,
                            const float* __restrict__ w_d1,
                            const float* __restrict__ w_d2,
                            float* __restrict__ base) {
    int o = blockIdx.x;
    int b = o / 6, t = o % 6, j = t % 3;
    const float* w = (t < 3) ? w_d1 : w_d2;
    int lane = threadIdx.x;
    float s = 0.0f;
    for (int c = lane; c < C2; c += 32) s += lat2[b * C2 + c] * w[c * 3 + j];
    #pragma unroll
    for (int off = 16; off > 0; off >>= 1) s += __shfl_xor_sync(0xffffffffu, s, off);
    if (lane == 0) base[b * 6 + t] = s;
}

__global__ void final_kernel(const float* __restrict__ base,
                             const float* __restrict__ w_d1, const float* __restrict__ b_d1,
                             const float* __restrict__ w_d2, const float* __restrict__ b_d2,
                             float* __restrict__ out) {
    int idx = blockIdx.x * blockDim.x + threadIdx.x;
    int b = idx >> 12, n = idx & 4095;
    int ix = n / 46, iy = n % 46;
    float y0 = 1.0f + ix * (119.0f / 90.0f);
    float y1 = 1.0f + iy * (59.0f / 45.0f);
    float kk[3];
    #pragma unroll
    for (int j = 0; j < 3; j++)
        kk[j] = selu_f(base[b * 6 + j] + y0 * w_d1[512 * 3 + j] + y1 * w_d1[513 * 3 + j] + b_d1[j]);
    #pragma unroll
    for (int j = 0; j < 3; j++) {
        float v = base[b * 6 + 3 + j]
                + kk[0] * w_d2[512 * 3 + j]
                + kk[1] * w_d2[513 * 3 + j]
                + kk[2] * w_d2[514 * 3 + j]
                + b_d2[j];
        out[(size_t)idx * 3 + j] = selu_f(v);
    }
}

// ---------------- launch ----------------
extern "C" void kernel_launch(void* const* d_in, const int* in_sizes, int n_in,
                              void* d_out, int out_size) {
    const float* x    = (const float*)d_in[0];
    const int*   knn  = (const int*)  d_in[1];
    const float* w_e1 = (const float*)d_in[2];
    const float* b_e1 = (const float*)d_in[3];
    const float* w_g1 = (const float*)d_in[4];
    const float* b_g1 = (const float*)d_in[5];
    const float* w_g2 = (const float*)d_in[6];
    const float* b_g2 = (const float*)d_in[7];
    const float* w_e2 = (const float*)d_in[8];
    const float* b_e2 = (const float*)d_in[9];
    const float* w_d1 = (const float*)d_in[10];
    const float* b_d1 = (const float*)d_in[11];
    const float* w_d2 = (const float*)d_in[12];
    const float* b_d2 = (const float*)d_in[13];
    float* out = (float*)d_out;
    const int* src = knn;
    const int* dst = knn + NEDGE;

    float *p_h0, *p_agg0, *p_h1, *p_agg1, *p_lat, *p_lat2, *p_base, *p_dinv;
    cudaGetSymbolAddress((void**)&p_h0,   g_h0);
    cudaGetSymbolAddress((void**)&p_agg0, g_agg0);
    cudaGetSymbolAddress((void**)&p_h1,   g_h1);
    cudaGetSymbolAddress((void**)&p_agg1, g_agg1);
    cudaGetSymbolAddress((void**)&p_lat,  g_lat);
    cudaGetSymbolAddress((void**)&p_lat2, g_lat2);
    cudaGetSymbolAddress((void**)&p_base, g_base);
    cudaGetSymbolAddress((void**)&p_dinv, g_dinv);

    init_kernel<<<BN / 256, 256>>>();
    cnt_kernel<<<NEDGE / 256, 256>>>(dst);
    scan_kernel<<<1, 1024>>>();
    fill_kernel<<<NEDGE / 256, 256>>>(src, dst);
    cov_e1_kernel<<<BN / 64, 128>>>(x, w_e1, b_e1);

    // GCN layer 1
    gather64_kernel<<<BN / 16, 256>>>(p_h0, p_agg0);
    gemm_tf32_kernel<C1, C0, false><<<dim3(C1 / 64, BN / 128), 256>>>(
        p_agg0, p_dinv, w_g1, b_g1, p_h1, nullptr);

    // GCN layer 2 + fused max-pool
    gather128_kernel<<<BN / 8, 256>>>(p_h1, p_agg1);
    gemm_tf32_kernel<C2, C1, true><<<dim3(C2 / 64, BN / 128), 256>>>(
        p_agg1, p_dinv, w_g2, b_g2, nullptr, p_lat);

    e2_kernel<<<NB, C2>>>(p_lat, w_e2, b_e2, p_lat2);
    base_kernel<<<NB * 6, 32>>>(p_lat2, w_d1, w_d2, p_base);
    final_kernel<<<BN / 256, 256>>>(p_base, w_d1, b_d1, w_d2, b_d2, out);
}

// round 5
// speedup vs baseline: 1.0002x; 1.0002x over previous
#include <cuda_runtime.h>
#include <math.h>
#include <stdint.h>

#define NB    8
#define NPTS  4096
#define BN    32768
#define NEDGE 524288
#define C0    64
#define C1    128
#define C2    512

// ---------------- scratch ----------------
__device__ float g_h0[BN * C0];
__device__ float g_agg0[BN * C0];
__device__ float g_h1[BN * C1];
__device__ float g_agg1[BN * C1];
__device__ float g_dinv[BN];
__device__ int   g_cnt[BN];
__device__ int   g_rowstart[BN + 1];
__device__ int   g_cur[BN];
__device__ int   g_el[NEDGE];
__device__ float g_lat[NB * C2];
__device__ float g_lat2[NB * C2];
__device__ float g_base[NB * 6];

__device__ __forceinline__ float selu_f(float v) {
    const float scale = 1.0507009873554805f;
    const float alpha = 1.6732632423543772f;
    return v > 0.0f ? scale * v : scale * alpha * expm1f(v);
}

__device__ __forceinline__ void atomicMaxF(float* addr, float v) {
    if (v >= 0.0f) atomicMax((int*)addr, __float_as_int(v));
    else           atomicMin((unsigned int*)addr, __float_as_uint(v));
}

__device__ __forceinline__ uint32_t f2tf32(float v) {
    uint32_t r;
    asm("cvt.rna.tf32.f32 %0, %1;" : "=r"(r) : "f"(v));
    return r;
}

__device__ __forceinline__ void mma_tf32(float d[4],
                                         uint32_t a0, uint32_t a1, uint32_t a2, uint32_t a3,
                                         uint32_t b0, uint32_t b1) {
    asm volatile("mma.sync.aligned.m16n8k8.row.col.f32.tf32.tf32.f32 "
                 "{%0,%1,%2,%3},{%4,%5,%6,%7},{%8,%9},{%0,%1,%2,%3};"
                 : "+f"(d[0]), "+f"(d[1]), "+f"(d[2]), "+f"(d[3])
                 : "r"(a0), "r"(a1), "r"(a2), "r"(a3), "r"(b0), "r"(b1));
}

__device__ __forceinline__ float4 ldg_nc4(const float4* p) {
    float4 v;
    asm volatile("ld.global.nc.v4.f32 {%0,%1,%2,%3}, [%4];"
                 : "=f"(v.x), "=f"(v.y), "=f"(v.z), "=f"(v.w) : "l"(p));
    return v;
}

// ---------------- init ----------------
__global__ void init_kernel() {
    int i = blockIdx.x * blockDim.x + threadIdx.x;
    if (i < BN) g_cnt[i] = 0;
    if (i < NB * C2) g_lat[i] = __int_as_float(0xff800000);
}
__global__ void cnt_kernel(const int* __restrict__ dst) {
    int e = blockIdx.x * blockDim.x + threadIdx.x;
    if (e < NEDGE) atomicAdd(&g_cnt[dst[e]], 1);
}

// ---------------- single-block scan: rowstart/cursor/dinv ----------------
__global__ void __launch_bounds__(1024) scan_kernel() {
    __shared__ int ssum[1024];
    int t = threadIdx.x;
    int base = t << 5;
    int local[32];
    int s = 0;
    #pragma unroll
    for (int j = 0; j < 32; j++) { local[j] = g_cnt[base + j]; s += local[j]; }
    ssum[t] = s;
    __syncthreads();
    for (int off = 1; off < 1024; off <<= 1) {
        int v = (t >= off) ? ssum[t - off] : 0;
        __syncthreads();
        ssum[t] += v;
        __syncthreads();
    }
    int run = ssum[t] - s;
    #pragma unroll
    for (int j = 0; j < 32; j++) {
        g_rowstart[base + j] = run;
        g_cur[base + j] = run;
        g_dinv[base + j] = rsqrtf((float)(local[j] + 1));
        run += local[j];
    }
    if (t == 1023) g_rowstart[BN] = run;
}

// ---------------- CSR fill ----------------
__global__ void fill_kernel(const int* __restrict__ src, const int* __restrict__ dst) {
    int e = blockIdx.x * blockDim.x + threadIdx.x;
    if (e >= NEDGE) return;
    int d = dst[e];
    int pos = atomicAdd(&g_cur[d], 1);
    g_el[pos] = src[e];
}

// ---------------- cov + 12->64 + selu -> hs0 ----------------
__global__ void __launch_bounds__(128)
cov_e1_kernel(const float* __restrict__ x,
              const float* __restrict__ w_e1,
              const float* __restrict__ b_e1) {
    __shared__ float xw[88][3];
    __shared__ float ws[12 * 64];
    __shared__ float bs[64];
    __shared__ float feat_s[64][13];
    __shared__ float out_s[64][68];
    int t = threadIdx.x;
    int blk = blockIdx.x;
    int b = blk >> 6;
    int n_base = (blk & 63) << 6;
    int point0 = blk << 6;

    for (int i = t; i < 88; i += 128) {
        int idx = n_base + i - 12;
        idx = min(max(idx, 0), NPTS - 1);
        const float* xp = x + (((size_t)b << 12) + idx) * 3;
        xw[i][0] = xp[0]; xw[i][1] = xp[1]; xw[i][2] = xp[2];
    }
    for (int i = t; i < 12 * 64; i += 128) ws[i] = w_e1[i];
    if (t < 64) bs[t] = b_e1[t];
    __syncthreads();

    if (t < 64) {
        int n = n_base + t;
        float m0 = 0.f, m1 = 0.f, m2 = 0.f, cnt = 0.f;
        #pragma unroll
        for (int w = 0; w < 25; w++) {
            int nn = n + w - 12;
            if (nn >= 0 && nn < NPTS) {
                m0 += xw[t + w][0]; m1 += xw[t + w][1]; m2 += xw[t + w][2];
                cnt += 1.0f;
            }
        }
        float ic = 1.0f / cnt;
        m0 *= ic; m1 *= ic; m2 *= ic;
        float c00=0,c01=0,c02=0,c11=0,c12=0,c22=0;
        #pragma unroll
        for (int w = 0; w < 25; w++) {
            int nn = n + w - 12;
            if (nn >= 0 && nn < NPTS) {
                float d0 = xw[t + w][0] - m0;
                float d1 = xw[t + w][1] - m1;
                float d2 = xw[t + w][2] - m2;
                c00 = fmaf(d0,d0,c00); c01 = fmaf(d0,d1,c01); c02 = fmaf(d0,d2,c02);
                c11 = fmaf(d1,d1,c11); c12 = fmaf(d1,d2,c12); c22 = fmaf(d2,d2,c22);
            }
        }
        const float s = 1.0f / 23.0f;
        feat_s[t][0] = xw[t + 12][0]; feat_s[t][1] = xw[t + 12][1]; feat_s[t][2] = xw[t + 12][2];
        feat_s[t][3] = c00 * s; feat_s[t][4]  = c01 * s; feat_s[t][5]  = c02 * s;
        feat_s[t][6] = c01 * s; feat_s[t][7]  = c11 * s; feat_s[t][8]  = c12 * s;
        feat_s[t][9] = c02 * s; feat_s[t][10] = c12 * s; feat_s[t][11] = c22 * s;
    }
    __syncthreads();

    int pt = t >> 1, half = t & 1;
    float dv = g_dinv[point0 + pt];
    float feat[12];
    #pragma unroll
    for (int k = 0; k < 12; k++) feat[k] = feat_s[pt][k];
    #pragma unroll 4
    for (int jj = 0; jj < 32; jj++) {
        int j = (half << 5) + jj;
        float acc = bs[j];
        #pragma unroll
        for (int k = 0; k < 12; k++) acc = fmaf(feat[k], ws[k * 64 + j], acc);
        out_s[pt][j] = dv * selu_f(acc);
    }
    __syncthreads();

    for (int i = t; i < 1024; i += 128) {
        int row = i >> 4, q = i & 15;
        float4 v = *reinterpret_cast<const float4*>(&out_s[row][q << 2]);
        *reinterpret_cast<float4*>(g_h0 + (size_t)(point0 + row) * 64 + (q << 2)) = v;
    }
}

// ---------------- CSR gather with MLP=8 index prefetch ----------------
// LOG4 = log2(float4 slots per node). node handled by (1<<LOG4) lanes.
template<int LOG4>
__global__ void __launch_bounds__(256)
gather_kernel(const float* __restrict__ hs, float* __restrict__ agg) {
    const float4* h4 = reinterpret_cast<const float4*>(hs);
    int t = threadIdx.x;
    int node = (blockIdx.x << (8 - LOG4)) + (t >> LOG4);
    int lane = t & ((1 << LOG4) - 1);
    int rs = g_rowstart[node], re = g_rowstart[node + 1];
    float4 acc = h4[((size_t)node << LOG4) + lane];

    int e = rs;
    // chunks of 8: prefetch indices, then batch row loads (MLP=8)
    for (; e + 8 <= re; e += 8) {
        int idx[8];
        #pragma unroll
        for (int j = 0; j < 8; j++) idx[j] = __ldg(g_el + e + j);
        float4 v[8];
        #pragma unroll
        for (int j = 0; j < 8; j++) v[j] = ldg_nc4(h4 + (((size_t)idx[j]) << LOG4) + lane);
        #pragma unroll
        for (int j = 0; j < 8; j++) {
            acc.x += v[j].x; acc.y += v[j].y; acc.z += v[j].z; acc.w += v[j].w;
        }
    }
    // remainder, chunks of 2
    int rem = re - e;
    if (rem >= 4) {
        int idx[4];
        #pragma unroll
        for (int j = 0; j < 4; j++) idx[j] = __ldg(g_el + e + j);
        float4 v[4];
        #pragma unroll
        for (int j = 0; j < 4; j++) v[j] = ldg_nc4(h4 + (((size_t)idx[j]) << LOG4) + lane);
        #pragma unroll
        for (int j = 0; j < 4; j++) {
            acc.x += v[j].x; acc.y += v[j].y; acc.z += v[j].z; acc.w += v[j].w;
        }
        e += 4;
    }
    for (; e < re; e++) {
        int s = __ldg(g_el + e);
        float4 v = ldg_nc4(h4 + (((size_t)s) << LOG4) + lane);
        acc.x += v.x; acc.y += v.y; acc.z += v.z; acc.w += v.w;
    }
    reinterpret_cast<float4*>(agg)[((size_t)node << LOG4) + lane] = acc;
}

// ---------------- 3xTF32 GEMM: out = selu( (dinv[row]*A[row]) @ W + bias ) ----------------
template<int N, int K, bool DO_MAX>
__global__ void __launch_bounds__(256, 2)
gemm_tf32_kernel(const float* __restrict__ A, const float* __restrict__ dinv,
                 const float* __restrict__ Wt, const float* __restrict__ bias,
                 float* __restrict__ O1, float* __restrict__ lat) {
    __shared__ float Ah[128][20];
    __shared__ float Al[128][20];
    __shared__ float Bh[16][72];
    __shared__ float Bl[16][72];

    int tid = threadIdx.x;
    int warp = tid >> 5, lane = tid & 31;
    int wm = warp >> 2, wn = warp & 3;
    int g = lane >> 2, c = lane & 3;
    int row0 = blockIdx.y * 128, col0 = blockIdx.x * 64;

    int ar = tid >> 1;
    float dv = dinv[row0 + ar];
    int bkr = tid >> 4;
    int bn4 = tid & 15;

    float d[4][2][4];
    #pragma unroll
    for (int mt = 0; mt < 4; mt++)
        #pragma unroll
        for (int nt = 0; nt < 2; nt++)
            #pragma unroll
            for (int r = 0; r < 4; r++) d[mt][nt][r] = 0.0f;

    for (int kt = 0; kt < K; kt += 16) {
        #pragma unroll
        for (int i = 0; i < 2; i++) {
            int q = ((tid & 1) << 1) + i;
            float4 av = *reinterpret_cast<const float4*>(A + (size_t)(row0 + ar) * K + kt + (q << 2));
            float vv[4] = {dv * av.x, dv * av.y, dv * av.z, dv * av.w};
            #pragma unroll
            for (int j = 0; j < 4; j++) {
                uint32_t hb = f2tf32(vv[j]);
                float hf = __uint_as_float(hb);
                Ah[ar][(q << 2) + j] = hf;
                Al[ar][(q << 2) + j] = __uint_as_float(f2tf32(vv[j] - hf));
            }
        }
        {
            float4 bv = *reinterpret_cast<const float4*>(Wt + (size_t)(kt + bkr) * N + col0 + (bn4 << 2));
            float vv[4] = {bv.x, bv.y, bv.z, bv.w};
            #pragma unroll
            for (int j = 0; j < 4; j++) {
                uint32_t hb = f2tf32(vv[j]);
                float hf = __uint_as_float(hb);
                Bh[bkr][(bn4 << 2) + j] = hf;
                Bl[bkr][(bn4 << 2) + j] = __uint_as_float(f2tf32(vv[j] - hf));
            }
        }
        __syncthreads();

        #pragma unroll
        for (int ks = 0; ks < 2; ks++) {
            int k0 = ks << 3;
            uint32_t ahi[4][4], alo[4][4];
            #pragma unroll
            for (int mt = 0; mt < 4; mt++) {
                int rm = wm * 64 + mt * 16;
                ahi[mt][0] = __float_as_uint(Ah[rm + g][k0 + c]);
                ahi[mt][1] = __float_as_uint(Ah[rm + g + 8][k0 + c]);
                ahi[mt][2] = __float_as_uint(Ah[rm + g][k0 + c + 4]);
                ahi[mt][3] = __float_as_uint(Ah[rm + g + 8][k0 + c + 4]);
                alo[mt][0] = __float_as_uint(Al[rm + g][k0 + c]);
                alo[mt][1] = __float_as_uint(Al[rm + g + 8][k0 + c]);
                alo[mt][2] = __float_as_uint(Al[rm + g][k0 + c + 4]);
                alo[mt][3] = __float_as_uint(Al[rm + g + 8][k0 + c + 4]);
            }
            uint32_t bhi[2][2], blo[2][2];
            #pragma unroll
            for (int nt = 0; nt < 2; nt++) {
                int nb = wn * 16 + nt * 8;
                bhi[nt][0] = __float_as_uint(Bh[k0 + c][nb + g]);
                bhi[nt][1] = __float_as_uint(Bh[k0 + c + 4][nb + g]);
                blo[nt][0] = __float_as_uint(Bl[k0 + c][nb + g]);
                blo[nt][1] = __float_as_uint(Bl[k0 + c + 4][nb + g]);
            }
            #pragma unroll
            for (int mt = 0; mt < 4; mt++)
                #pragma unroll
                for (int nt = 0; nt < 2; nt++) {
                    mma_tf32(d[mt][nt], ahi[mt][0], ahi[mt][1], ahi[mt][2], ahi[mt][3],
                             bhi[nt][0], bhi[nt][1]);
                    mma_tf32(d[mt][nt], ahi[mt][0], ahi[mt][1], ahi[mt][2], ahi[mt][3],
                             blo[nt][0], blo[nt][1]);
                    mma_tf32(d[mt][nt], alo[mt][0], alo[mt][1], alo[mt][2], alo[mt][3],
                             bhi[nt][0], bhi[nt][1]);
                }
        }
        __syncthreads();
    }

    float bv[2][2];
    #pragma unroll
    for (int nt = 0; nt < 2; nt++) {
        int cc = col0 + wn * 16 + nt * 8 + (c << 1);
        bv[nt][0] = bias[cc];
        bv[nt][1] = bias[cc + 1];
    }

    if (!DO_MAX) {
        #pragma unroll
        for (int mt = 0; mt < 4; mt++) {
            int rbase = row0 + wm * 64 + mt * 16;
            #pragma unroll
            for (int half = 0; half < 2; half++) {
                int r = rbase + g + half * 8;
                float dv2 = dinv[r];
                #pragma unroll
                for (int nt = 0; nt < 2; nt++) {
                    int cc = col0 + wn * 16 + nt * 8 + (c << 1);
                    float2 o;
                    o.x = dv2 * selu_f(d[mt][nt][half * 2 + 0] + bv[nt][0]);
                    o.y = dv2 * selu_f(d[mt][nt][half * 2 + 1] + bv[nt][1]);
                    *reinterpret_cast<float2*>(O1 + (size_t)r * N + cc) = o;
                }
            }
        }
    } else {
        float mv[2][2];
        #pragma unroll
        for (int nt = 0; nt < 2; nt++) { mv[nt][0] = mv[nt][1] = __int_as_float(0xff800000); }
        #pragma unroll
        for (int mt = 0; mt < 4; mt++)
            #pragma unroll
            for (int nt = 0; nt < 2; nt++) {
                mv[nt][0] = fmaxf(mv[nt][0], fmaxf(selu_f(d[mt][nt][0] + bv[nt][0]),
                                                   selu_f(d[mt][nt][2] + bv[nt][0])));
                mv[nt][1] = fmaxf(mv[nt][1], fmaxf(selu_f(d[mt][nt][1] + bv[nt][1]),
                                                   selu_f(d[mt][nt][3] + bv[nt][1])));
            }
        #pragma unroll
        for (int off = 4; off <= 16; off <<= 1)
            #pragma unroll
            for (int nt = 0; nt < 2; nt++) {
                mv[nt][0] = fmaxf(mv[nt][0], __shfl_xor_sync(0xffffffffu, mv[nt][0], off));
                mv[nt][1] = fmaxf(mv[nt][1], __shfl_xor_sync(0xffffffffu, mv[nt][1], off));
            }
        if (lane < 4) {
            int b = row0 >> 12;
            #pragma unroll
            for (int nt = 0; nt < 2; nt++) {
                int cc = col0 + wn * 16 + nt * 8 + (lane << 1);
                atomicMaxF(&lat[b * C2 + cc], mv[nt][0]);
                atomicMaxF(&lat[b * C2 + cc + 1], mv[nt][1]);
            }
        }
    }
}

// ---------------- lat2 = selu(lat @ w_e2 + b_e2) ----------------
__global__ void e2_kernel(const float* __restrict__ lat, const float* __restrict__ w,
                          const float* __restrict__ bias, float* __restrict__ lat2) {
    __shared__ float row[C2];
    int c = threadIdx.x;
    row[c] = lat[blockIdx.x * C2 + c];
    __syncthreads();
    float acc = bias[c];
    #pragma unroll 8
    for (int k = 0; k < C2; k++) acc = fmaf(row[k], w[k * C2 + c], acc);
    lat2[blockIdx.x * C2 + c] = selu_f(acc);
}

// ---------------- decoder ----------------
__global__ void base_kernel(const float* __restrict__ lat2,
                            const float* __restrict__ w_d1,
                            const float* __restrict__ w_d2,
                            float* __restrict__ base) {
    int o = blockIdx.x;
    int b = o / 6, t = o % 6, j = t % 3;
    const float* w = (t < 3) ? w_d1 : w_d2;
    int lane = threadIdx.x;
    float s = 0.0f;
    for (int c = lane; c < C2; c += 32) s += lat2[b * C2 + c] * w[c * 3 + j];
    #pragma unroll
    for (int off = 16; off > 0; off >>= 1) s += __shfl_xor_sync(0xffffffffu, s, off);
    if (lane == 0) base[b * 6 + t] = s;
}

__global__ void final_kernel(const float* __restrict__ base,
                             const float* __restrict__ w_d1, const float* __restrict__ b_d1,
                             const float* __restrict__ w_d2, const float* __restrict__ b_d2,
                             float* __restrict__ out) {
    int idx = blockIdx.x * blockDim.x + threadIdx.x;
    int b = idx >> 12, n = idx & 4095;
    int ix = n / 46, iy = n % 46;
    float y0 = 1.0f + ix * (119.0f / 90.0f);
    float y1 = 1.0f + iy * (59.0f / 45.0f);
    float kk[3];
    #pragma unroll
    for (int j = 0; j < 3; j++)
        kk[j] = selu_f(base[b * 6 + j] + y0 * w_d1[512 * 3 + j] + y1 * w_d1[513 * 3 + j] + b_d1[j]);
    #pragma unroll
    for (int j = 0; j < 3; j++) {
        float v = base[b * 6 + 3 + j]
                + kk[0] * w_d2[512 * 3 + j]
                + kk[1] * w_d2[513 * 3 + j]
                + kk[2] * w_d2[514 * 3 + j]
                + b_d2[j];
        out[(size_t)idx * 3 + j] = selu_f(v);
    }
}

// ---------------- launch ----------------
extern "C" void kernel_launch(void* const* d_in, const int* in_sizes, int n_in,
                              void* d_out, int out_size) {
    const float* x    = (const float*)d_in[0];
    const int*   knn  = (const int*)  d_in[1];
    const float* w_e1 = (const float*)d_in[2];
    const float* b_e1 = (const float*)d_in[3];
    const float* w_g1 = (const float*)d_in[4];
    const float* b_g1 = (const float*)d_in[5];
    const float* w_g2 = (const float*)d_in[6];
    const float* b_g2 = (const float*)d_in[7];
    const float* w_e2 = (const float*)d_in[8];
    const float* b_e2 = (const float*)d_in[9];
    const float* w_d1 = (const float*)d_in[10];
    const float* b_d1 = (const float*)d_in[11];
    const float* w_d2 = (const float*)d_in[12];
    const float* b_d2 = (const float*)d_in[13];
    float* out = (float*)d_out;
    const int* src = knn;
    const int* dst = knn + NEDGE;

    float *p_h0, *p_agg0, *p_h1, *p_agg1, *p_lat, *p_lat2, *p_base, *p_dinv;
    cudaGetSymbolAddress((void**)&p_h0,   g_h0);
    cudaGetSymbolAddress((void**)&p_agg0, g_agg0);
    cudaGetSymbolAddress((void**)&p_h1,   g_h1);
    cudaGetSymbolAddress((void**)&p_agg1, g_agg1);
    cudaGetSymbolAddress((void**)&p_lat,  g_lat);
    cudaGetSymbolAddress((void**)&p_lat2, g_lat2);
    cudaGetSymbolAddress((void**)&p_base, g_base);
    cudaGetSymbolAddress((void**)&p_dinv, g_dinv);

    init_kernel<<<BN / 256, 256>>>();
    cnt_kernel<<<NEDGE / 256, 256>>>(dst);
    scan_kernel<<<1, 1024>>>();
    fill_kernel<<<NEDGE / 256, 256>>>(src, dst);
    cov_e1_kernel<<<BN / 64, 128>>>(x, w_e1, b_e1);

    // GCN layer 1: gather width 64 (16 float4 lanes per node)
    gather_kernel<4><<<BN / 16, 256>>>(p_h0, p_agg0);
    gemm_tf32_kernel<C1, C0, false><<<dim3(C1 / 64, BN / 128), 256>>>(
        p_agg0, p_dinv, w_g1, b_g1, p_h1, nullptr);

    // GCN layer 2 + fused max-pool: gather width 128 (32 float4 lanes per node)
    gather_kernel<5><<<BN / 8, 256>>>(p_h1, p_agg1);
    gemm_tf32_kernel<C2, C1, true><<<dim3(C2 / 64, BN / 128), 256>>>(
        p_agg1, p_dinv, w_g2, b_g2, nullptr, p_lat);

    e2_kernel<<<NB, C2>>>(p_lat, w_e2, b_e2, p_lat2);
    base_kernel<<<NB * 6, 32>>>(p_lat2, w_d1, w_d2, p_base);
    final_kernel<<<BN / 256, 256>>>(p_base, w_d1, b_d1, w_d2, b_d2, out);
}

// round 6
// speedup vs baseline: 1.4166x; 1.4163x over previous
#include <cuda_runtime.h>
#include <math.h>
#include <stdint.h>

#define NB    8
#define NPTS  4096
#define BN    32768
#define NEDGE 524288
#define C0    64
#define C1    128
#define C2    512

// ---------------- scratch ----------------
__device__ float g_h0[BN * C0];      // hs0 = dinv * h0
__device__ float g_agg0[BN * C0];    // starts as hs0 (self loop), edges add
__device__ float g_h1[BN * C1];
__device__ float g_agg1[BN * C1];
__device__ float g_dinv[BN];
__device__ int   g_deg[BN];
__device__ float g_lat[NB * C2];
__device__ float g_lat2[NB * C2];
__device__ float g_base[NB * 6];

__device__ __forceinline__ float selu_f(float v) {
    const float scale = 1.0507009873554805f;
    const float alpha = 1.6732632423543772f;
    return v > 0.0f ? scale * v : scale * alpha * expm1f(v);
}

__device__ __forceinline__ void atomicMaxF(float* addr, float v) {
    if (v >= 0.0f) atomicMax((int*)addr, __float_as_int(v));
    else           atomicMin((unsigned int*)addr, __float_as_uint(v));
}

__device__ __forceinline__ void red_add_v4(float* p, float4 v) {
    asm volatile("red.global.add.v4.f32 [%0], {%1,%2,%3,%4};"
                 :: "l"(p), "f"(v.x), "f"(v.y), "f"(v.z), "f"(v.w) : "memory");
}

__device__ __forceinline__ float f2tf32f(float v) {
    uint32_t r;
    asm("cvt.rna.tf32.f32 %0, %1;" : "=r"(r) : "f"(v));
    return __uint_as_float(r);
}

__device__ __forceinline__ void mma_tf32(float d[4],
                                         uint32_t a0, uint32_t a1, uint32_t a2, uint32_t a3,
                                         uint32_t b0, uint32_t b1) {
    asm volatile("mma.sync.aligned.m16n8k8.row.col.f32.tf32.tf32.f32 "
                 "{%0,%1,%2,%3},{%4,%5,%6,%7},{%8,%9},{%0,%1,%2,%3};"
                 : "+f"(d[0]), "+f"(d[1]), "+f"(d[2]), "+f"(d[3])
                 : "r"(a0), "r"(a1), "r"(a2), "r"(a3), "r"(b0), "r"(b1));
}

// ---------------- init / degree ----------------
__global__ void init_kernel() {
    int i = blockIdx.x * blockDim.x + threadIdx.x;
    if (i < BN) g_deg[i] = 1;
    if (i < NB * C2) g_lat[i] = __int_as_float(0xff800000);
}
__global__ void deg_kernel(const int* __restrict__ dst) {
    int e = blockIdx.x * blockDim.x + threadIdx.x;
    if (e < NEDGE) atomicAdd(&g_deg[dst[e]], 1);
}
__global__ void dinv_kernel() {
    int i = blockIdx.x * blockDim.x + threadIdx.x;
    if (i < BN) g_dinv[i] = rsqrtf((float)g_deg[i]);
}

// ---------------- cov + 12->64 + selu -> hs0 (writes h0 AND agg0) ----------------
__global__ void __launch_bounds__(128)
cov_e1_kernel(const float* __restrict__ x,
              const float* __restrict__ w_e1,
              const float* __restrict__ b_e1) {
    __shared__ float xw[88][3];
    __shared__ float ws[12 * 64];
    __shared__ float bs[64];
    __shared__ float feat_s[64][13];
    __shared__ float out_s[64][68];
    int t = threadIdx.x;
    int blk = blockIdx.x;
    int b = blk >> 6;
    int n_base = (blk & 63) << 6;
    int point0 = blk << 6;

    for (int i = t; i < 88; i += 128) {
        int idx = n_base + i - 12;
        idx = min(max(idx, 0), NPTS - 1);
        const float* xp = x + (((size_t)b << 12) + idx) * 3;
        xw[i][0] = xp[0]; xw[i][1] = xp[1]; xw[i][2] = xp[2];
    }
    for (int i = t; i < 12 * 64; i += 128) ws[i] = w_e1[i];
    if (t < 64) bs[t] = b_e1[t];
    __syncthreads();

    if (t < 64) {
        int n = n_base + t;
        float m0 = 0.f, m1 = 0.f, m2 = 0.f, cnt = 0.f;
        #pragma unroll
        for (int w = 0; w < 25; w++) {
            int nn = n + w - 12;
            if (nn >= 0 && nn < NPTS) {
                m0 += xw[t + w][0]; m1 += xw[t + w][1]; m2 += xw[t + w][2];
                cnt += 1.0f;
            }
        }
        float ic = 1.0f / cnt;
        m0 *= ic; m1 *= ic; m2 *= ic;
        float c00=0,c01=0,c02=0,c11=0,c12=0,c22=0;
        #pragma unroll
        for (int w = 0; w < 25; w++) {
            int nn = n + w - 12;
            if (nn >= 0 && nn < NPTS) {
                float d0 = xw[t + w][0] - m0;
                float d1 = xw[t + w][1] - m1;
                float d2 = xw[t + w][2] - m2;
                c00 = fmaf(d0,d0,c00); c01 = fmaf(d0,d1,c01); c02 = fmaf(d0,d2,c02);
                c11 = fmaf(d1,d1,c11); c12 = fmaf(d1,d2,c12); c22 = fmaf(d2,d2,c22);
            }
        }
        const float s = 1.0f / 23.0f;
        feat_s[t][0] = xw[t + 12][0]; feat_s[t][1] = xw[t + 12][1]; feat_s[t][2] = xw[t + 12][2];
        feat_s[t][3] = c00 * s; feat_s[t][4]  = c01 * s; feat_s[t][5]  = c02 * s;
        feat_s[t][6] = c01 * s; feat_s[t][7]  = c11 * s; feat_s[t][8]  = c12 * s;
        feat_s[t][9] = c02 * s; feat_s[t][10] = c12 * s; feat_s[t][11] = c22 * s;
    }
    __syncthreads();

    int pt = t >> 1, half = t & 1;
    float dv = g_dinv[point0 + pt];
    float feat[12];
    #pragma unroll
    for (int k = 0; k < 12; k++) feat[k] = feat_s[pt][k];
    #pragma unroll 4
    for (int jj = 0; jj < 32; jj++) {
        int j = (half << 5) + jj;
        float acc = bs[j];
        #pragma unroll
        for (int k = 0; k < 12; k++) acc = fmaf(feat[k], ws[k * 64 + j], acc);
        out_s[pt][j] = dv * selu_f(acc);
    }
    __syncthreads();

    for (int i = t; i < 1024; i += 128) {
        int row = i >> 4, q = i & 15;
        float4 v = *reinterpret_cast<const float4*>(&out_s[row][q << 2]);
        size_t gaddr = (size_t)(point0 + row) * 64 + (q << 2);
        *reinterpret_cast<float4*>(g_h0 + gaddr)   = v;
        *reinterpret_cast<float4*>(g_agg0 + gaddr) = v;
    }
}

// ---------------- edge scatter: agg[d] += hs[s] (vector red) ----------------
template<int LOGG>
__global__ void edge_kernel(const int* __restrict__ src, const int* __restrict__ dst,
                            const float* __restrict__ hs, float* __restrict__ agg) {
    int idx = blockIdx.x * blockDim.x + threadIdx.x;
    int e = idx >> LOGG;
    int g = idx & ((1 << LOGG) - 1);
    if (e >= NEDGE) return;
    int s = src[e], d = dst[e];
    float4 v = *reinterpret_cast<const float4*>(hs + ((size_t)s << (LOGG + 2)) + (g << 2));
    red_add_v4(agg + ((size_t)d << (LOGG + 2)) + (g << 2), v);
}

// ---------------- single-pass TF32 GEMM: out = selu( (dinv[row]*A[row]) @ W + b ) ----------------
// Block 128(M) x 64(N), KTILE=16, 256 threads = 8 warps (wm 0..1, wn 0..3),
// warp tile 64x16, mma m16n8k8.
template<int N, int K, bool DO_MAX>
__global__ void __launch_bounds__(256, 2)
gemm_tf32_kernel(const float* __restrict__ A, const float* __restrict__ dinv,
                 const float* __restrict__ Wt, const float* __restrict__ bias,
                 float* __restrict__ O1, float* __restrict__ O2,
                 float* __restrict__ lat) {
    __shared__ float Ah[128][20];
    __shared__ float Bh[16][72];

    int tid = threadIdx.x;
    int warp = tid >> 5, lane = tid & 31;
    int wm = warp >> 2, wn = warp & 3;
    int g = lane >> 2, c = lane & 3;
    int row0 = blockIdx.y * 128, col0 = blockIdx.x * 64;

    int ar = tid >> 1;                  // A row 0..127
    float dv = dinv[row0 + ar];
    int bkr = tid >> 4;                 // B k-row 0..15
    int bn4 = tid & 15;                 // B float4 col

    float d[4][2][4];
    #pragma unroll
    for (int mt = 0; mt < 4; mt++)
        #pragma unroll
        for (int nt = 0; nt < 2; nt++)
            #pragma unroll
            for (int r = 0; r < 4; r++) d[mt][nt][r] = 0.0f;

    for (int kt = 0; kt < K; kt += 16) {
        #pragma unroll
        for (int i = 0; i < 2; i++) {
            int q = ((tid & 1) << 1) + i;
            float4 av = *reinterpret_cast<const float4*>(A + (size_t)(row0 + ar) * K + kt + (q << 2));
            Ah[ar][(q << 2) + 0] = f2tf32f(dv * av.x);
            Ah[ar][(q << 2) + 1] = f2tf32f(dv * av.y);
            Ah[ar][(q << 2) + 2] = f2tf32f(dv * av.z);
            Ah[ar][(q << 2) + 3] = f2tf32f(dv * av.w);
        }
        {
            float4 bv = *reinterpret_cast<const float4*>(Wt + (size_t)(kt + bkr) * N + col0 + (bn4 << 2));
            Bh[bkr][(bn4 << 2) + 0] = f2tf32f(bv.x);
            Bh[bkr][(bn4 << 2) + 1] = f2tf32f(bv.y);
            Bh[bkr][(bn4 << 2) + 2] = f2tf32f(bv.z);
            Bh[bkr][(bn4 << 2) + 3] = f2tf32f(bv.w);
        }
        __syncthreads();

        #pragma unroll
        for (int ks = 0; ks < 2; ks++) {
            int k0 = ks << 3;
            uint32_t ahi[4][4];
            #pragma unroll
            for (int mt = 0; mt < 4; mt++) {
                int rm = wm * 64 + mt * 16;
                ahi[mt][0] = __float_as_uint(Ah[rm + g][k0 + c]);
                ahi[mt][1] = __float_as_uint(Ah[rm + g + 8][k0 + c]);
                ahi[mt][2] = __float_as_uint(Ah[rm + g][k0 + c + 4]);
                ahi[mt][3] = __float_as_uint(Ah[rm + g + 8][k0 + c + 4]);
            }
            uint32_t bhi[2][2];
            #pragma unroll
            for (int nt = 0; nt < 2; nt++) {
                int nb = wn * 16 + nt * 8;
                bhi[nt][0] = __float_as_uint(Bh[k0 + c][nb + g]);
                bhi[nt][1] = __float_as_uint(Bh[k0 + c + 4][nb + g]);
            }
            #pragma unroll
            for (int mt = 0; mt < 4; mt++)
                #pragma unroll
                for (int nt = 0; nt < 2; nt++)
                    mma_tf32(d[mt][nt], ahi[mt][0], ahi[mt][1], ahi[mt][2], ahi[mt][3],
                             bhi[nt][0], bhi[nt][1]);
        }
        __syncthreads();
    }

    float bv[2][2];
    #pragma unroll
    for (int nt = 0; nt < 2; nt++) {
        int cc = col0 + wn * 16 + nt * 8 + (c << 1);
        bv[nt][0] = bias[cc];
        bv[nt][1] = bias[cc + 1];
    }

    if (!DO_MAX) {
        #pragma unroll
        for (int mt = 0; mt < 4; mt++) {
            int rbase = row0 + wm * 64 + mt * 16;
            #pragma unroll
            for (int half = 0; half < 2; half++) {
                int r = rbase + g + half * 8;
                float dv2 = dinv[r];
                #pragma unroll
                for (int nt = 0; nt < 2; nt++) {
                    int cc = col0 + wn * 16 + nt * 8 + (c << 1);
                    float2 o;
                    o.x = dv2 * selu_f(d[mt][nt][half * 2 + 0] + bv[nt][0]);
                    o.y = dv2 * selu_f(d[mt][nt][half * 2 + 1] + bv[nt][1]);
                    size_t addr = (size_t)r * N + cc;
                    *reinterpret_cast<float2*>(O1 + addr) = o;
                    *reinterpret_cast<float2*>(O2 + addr) = o;
                }
            }
        }
    } else {
        float mv[2][2];
        #pragma unroll
        for (int nt = 0; nt < 2; nt++) { mv[nt][0] = mv[nt][1] = __int_as_float(0xff800000); }
        #pragma unroll
        for (int mt = 0; mt < 4; mt++)
            #pragma unroll
            for (int nt = 0; nt < 2; nt++) {
                mv[nt][0] = fmaxf(mv[nt][0], fmaxf(selu_f(d[mt][nt][0] + bv[nt][0]),
                                                   selu_f(d[mt][nt][2] + bv[nt][0])));
                mv[nt][1] = fmaxf(mv[nt][1], fmaxf(selu_f(d[mt][nt][1] + bv[nt][1]),
                                                   selu_f(d[mt][nt][3] + bv[nt][1])));
            }
        #pragma unroll
        for (int off = 4; off <= 16; off <<= 1)
            #pragma unroll
            for (int nt = 0; nt < 2; nt++) {
                mv[nt][0] = fmaxf(mv[nt][0], __shfl_xor_sync(0xffffffffu, mv[nt][0], off));
                mv[nt][1] = fmaxf(mv[nt][1], __shfl_xor_sync(0xffffffffu, mv[nt][1], off));
            }
        if (lane < 4) {
            int b = row0 >> 12;
            #pragma unroll
            for (int nt = 0; nt < 2; nt++) {
                int cc = col0 + wn * 16 + nt * 8 + (lane << 1);
                atomicMaxF(&lat[b * C2 + cc], mv[nt][0]);
                atomicMaxF(&lat[b * C2 + cc + 1], mv[nt][1]);
            }
        }
    }
}

// ---------------- lat2 = selu(lat @ w_e2 + b_e2) ----------------
__global__ void e2_kernel(const float* __restrict__ lat, const float* __restrict__ w,
                          const float* __restrict__ bias, float* __restrict__ lat2) {
    __shared__ float row[C2];
    int c = threadIdx.x;
    row[c] = lat[blockIdx.x * C2 + c];
    __syncthreads();
    float acc = bias[c];
    #pragma unroll 8
    for (int k = 0; k < C2; k++) acc = fmaf(row[k], w[k * C2 + c], acc);
    lat2[blockIdx.x * C2 + c] = selu_f(acc);
}

// ---------------- decoder ----------------
__global__ void base_kernel(const float* __restrict__ lat2,
                            const float* __restrict__ w_d1,
                            const float* __restrict__ w_d2,
                            float* __restrict__ base) {
    int o = blockIdx.x;
    int b = o / 6, t = o % 6, j = t % 3;
    const float* w = (t < 3) ? w_d1 : w_d2;
    int lane = threadIdx.x;
    float s = 0.0f;
    for (int c = lane; c < C2; c += 32) s += lat2[b * C2 + c] * w[c * 3 + j];
    #pragma unroll
    for (int off = 16; off > 0; off >>= 1) s += __shfl_xor_sync(0xffffffffu, s, off);
    if (lane == 0) base[b * 6 + t] = s;
}

__global__ void final_kernel(const float* __restrict__ base,
                             const float* __restrict__ w_d1, const float* __restrict__ b_d1,
                             const float* __restrict__ w_d2, const float* __restrict__ b_d2,
                             float* __restrict__ out) {
    int idx = blockIdx.x * blockDim.x + threadIdx.x;
    int b = idx >> 12, n = idx & 4095;
    int ix = n / 46, iy = n % 46;
    float y0 = 1.0f + ix * (119.0f / 90.0f);
    float y1 = 1.0f + iy * (59.0f / 45.0f);
    float kk[3];
    #pragma unroll
    for (int j = 0; j < 3; j++)
        kk[j] = selu_f(base[b * 6 + j] + y0 * w_d1[512 * 3 + j] + y1 * w_d1[513 * 3 + j] + b_d1[j]);
    #pragma unroll
    for (int j = 0; j < 3; j++) {
        float v = base[b * 6 + 3 + j]
                + kk[0] * w_d2[512 * 3 + j]
                + kk[1] * w_d2[513 * 3 + j]
                + kk[2] * w_d2[514 * 3 + j]
                + b_d2[j];
        out[(size_t)idx * 3 + j] = selu_f(v);
    }
}

// ---------------- launch ----------------
extern "C" void kernel_launch(void* const* d_in, const int* in_sizes, int n_in,
                              void* d_out, int out_size) {
    const float* x    = (const float*)d_in[0];
    const int*   knn  = (const int*)  d_in[1];
    const float* w_e1 = (const float*)d_in[2];
    const float* b_e1 = (const float*)d_in[3];
    const float* w_g1 = (const float*)d_in[4];
    const float* b_g1 = (const float*)d_in[5];
    const float* w_g2 = (const float*)d_in[6];
    const float* b_g2 = (const float*)d_in[7];
    const float* w_e2 = (const float*)d_in[8];
    const float* b_e2 = (const float*)d_in[9];
    const float* w_d1 = (const float*)d_in[10];
    const float* b_d1 = (const float*)d_in[11];
    const float* w_d2 = (const float*)d_in[12];
    const float* b_d2 = (const float*)d_in[13];
    float* out = (float*)d_out;
    const int* src = knn;
    const int* dst = knn + NEDGE;

    float *p_h0, *p_agg0, *p_h1, *p_agg1, *p_lat, *p_lat2, *p_base, *p_dinv;
    cudaGetSymbolAddress((void**)&p_h0,   g_h0);
    cudaGetSymbolAddress((void**)&p_agg0, g_agg0);
    cudaGetSymbolAddress((void**)&p_h1,   g_h1);
    cudaGetSymbolAddress((void**)&p_agg1, g_agg1);
    cudaGetSymbolAddress((void**)&p_lat,  g_lat);
    cudaGetSymbolAddress((void**)&p_lat2, g_lat2);
    cudaGetSymbolAddress((void**)&p_base, g_base);
    cudaGetSymbolAddress((void**)&p_dinv, g_dinv);

    init_kernel<<<BN / 256, 256>>>();
    deg_kernel<<<NEDGE / 256, 256>>>(dst);
    dinv_kernel<<<BN / 256, 256>>>();
    cov_e1_kernel<<<BN / 64, 128>>>(x, w_e1, b_e1);

    // GCN layer 1
    edge_kernel<4><<<(NEDGE * 16) / 256, 256>>>(src, dst, p_h0, p_agg0);
    gemm_tf32_kernel<C1, C0, false><<<dim3(C1 / 64, BN / 128), 256>>>(
        p_agg0, p_dinv, w_g1, b_g1, p_h1, p_agg1, nullptr);

    // GCN layer 2 + fused max-pool
    edge_kernel<5><<<(NEDGE * 32) / 256, 256>>>(src, dst, p_h1, p_agg1);
    gemm_tf32_kernel<C2, C1, true><<<dim3(C2 / 64, BN / 128), 256>>>(
        p_agg1, p_dinv, w_g2, b_g2, nullptr, nullptr, p_lat);

    e2_kernel<<<NB, C2>>>(p_lat, w_e2, b_e2, p_lat2);
    base_kernel<<<NB * 6, 32>>>(p_lat2, w_d1, w_d2, p_base);
    final_kernel<<<BN / 256, 256>>>(p_base, w_d1, b_d1, w_d2, b_d2, out);
}

// round 7
// speedup vs baseline: 1.5729x; 1.1103x over previous
#include <cuda_runtime.h>
#include <math.h>
#include <stdint.h>

#define NB    8
#define NPTS  4096
#define BN    32768
#define NEDGE 524288
#define C0    64
#define C1    128
#define C2    512

// ---------------- scratch ----------------
__device__ float g_h0[BN * C0];      // hs0 = dinv * h0
__device__ float g_agg0[BN * C0];    // seeded with hs0 (self loop), edges add
__device__ float g_h1[BN * C1];
__device__ float g_agg1[BN * C1];
__device__ float g_dinv[BN];
__device__ int   g_deg[BN];
__device__ float g_lat[NB * C2];
__device__ float g_lat2[NB * C2];
__device__ float g_base[NB * 6];

__device__ __forceinline__ float selu_f(float v) {
    const float scale = 1.0507009873554805f;
    const float alpha = 1.6732632423543772f;
    return v > 0.0f ? scale * v : scale * alpha * expm1f(v);
}

__device__ __forceinline__ void atomicMaxF(float* addr, float v) {
    if (v >= 0.0f) atomicMax((int*)addr, __float_as_int(v));
    else           atomicMin((unsigned int*)addr, __float_as_uint(v));
}

__device__ __forceinline__ void red_add_v4(float* p, float4 v) {
    asm volatile("red.global.add.v4.f32 [%0], {%1,%2,%3,%4};"
                 :: "l"(p), "f"(v.x), "f"(v.y), "f"(v.z), "f"(v.w) : "memory");
}

__device__ __forceinline__ float f2tf32f(float v) {
    uint32_t r;
    asm("cvt.rna.tf32.f32 %0, %1;" : "=r"(r) : "f"(v));
    return __uint_as_float(r);
}

__device__ __forceinline__ float4 ldg_nc4(const float4* p) {
    float4 v;
    asm volatile("ld.global.nc.v4.f32 {%0,%1,%2,%3}, [%4];"
                 : "=f"(v.x), "=f"(v.y), "=f"(v.z), "=f"(v.w) : "l"(p));
    return v;
}

__device__ __forceinline__ void mma_tf32(float d[4],
                                         uint32_t a0, uint32_t a1, uint32_t a2, uint32_t a3,
                                         uint32_t b0, uint32_t b1) {
    asm volatile("mma.sync.aligned.m16n8k8.row.col.f32.tf32.tf32.f32 "
                 "{%0,%1,%2,%3},{%4,%5,%6,%7},{%8,%9},{%0,%1,%2,%3};"
                 : "+f"(d[0]), "+f"(d[1]), "+f"(d[2]), "+f"(d[3])
                 : "r"(a0), "r"(a1), "r"(a2), "r"(a3), "r"(b0), "r"(b1));
}

// ---------------- init / degree ----------------
__global__ void init_kernel() {
    int i = blockIdx.x * blockDim.x + threadIdx.x;
    if (i < BN) g_deg[i] = 1;
    if (i < NB * C2) g_lat[i] = __int_as_float(0xff800000);
}
__global__ void deg_kernel(const int* __restrict__ dst) {
    int e = blockIdx.x * blockDim.x + threadIdx.x;
    if (e < NEDGE) atomicAdd(&g_deg[dst[e]], 1);
}
__global__ void dinv_kernel() {
    int i = blockIdx.x * blockDim.x + threadIdx.x;
    if (i < BN) g_dinv[i] = rsqrtf((float)g_deg[i]);
}

// ---------------- cov + 12->64 + selu -> hs0 (writes h0 AND agg0) ----------------
// 128 threads, 32 points per block, 4 threads share one point's 64-col matmul.
__global__ void __launch_bounds__(128)
cov_e1_kernel(const float* __restrict__ x,
              const float* __restrict__ w_e1,
              const float* __restrict__ b_e1) {
    __shared__ float xw[56][3];
    __shared__ float ws[12 * 64];
    __shared__ float bs[64];
    __shared__ float feat_s[32][13];
    __shared__ float out_s[32][68];
    int t = threadIdx.x;
    int blk = blockIdx.x;
    int b = blk >> 7;                 // 128 blocks per batch
    int n_base = (blk & 127) << 5;    // batch-local start (32 points)
    int point0 = blk << 5;

    if (t < 56) {
        int idx = n_base + t - 12;
        idx = min(max(idx, 0), NPTS - 1);
        const float* xp = x + (((size_t)b << 12) + idx) * 3;
        xw[t][0] = xp[0]; xw[t][1] = xp[1]; xw[t][2] = xp[2];
    }
    {
        // 768 weights, 128 threads -> 6 each
        for (int i = t; i < 12 * 64; i += 128) ws[i] = w_e1[i];
        if (t < 64) bs[t] = b_e1[t];
    }
    __syncthreads();

    if (t < 32) {
        int n = n_base + t;
        float m0 = 0.f, m1 = 0.f, m2 = 0.f, cnt = 0.f;
        #pragma unroll
        for (int w = 0; w < 25; w++) {
            int nn = n + w - 12;
            if (nn >= 0 && nn < NPTS) {
                m0 += xw[t + w][0]; m1 += xw[t + w][1]; m2 += xw[t + w][2];
                cnt += 1.0f;
            }
        }
        float ic = 1.0f / cnt;
        m0 *= ic; m1 *= ic; m2 *= ic;
        float c00=0,c01=0,c02=0,c11=0,c12=0,c22=0;
        #pragma unroll
        for (int w = 0; w < 25; w++) {
            int nn = n + w - 12;
            if (nn >= 0 && nn < NPTS) {
                float d0 = xw[t + w][0] - m0;
                float d1 = xw[t + w][1] - m1;
                float d2 = xw[t + w][2] - m2;
                c00 = fmaf(d0,d0,c00); c01 = fmaf(d0,d1,c01); c02 = fmaf(d0,d2,c02);
                c11 = fmaf(d1,d1,c11); c12 = fmaf(d1,d2,c12); c22 = fmaf(d2,d2,c22);
            }
        }
        const float s = 1.0f / 23.0f;
        feat_s[t][0] = xw[t + 12][0]; feat_s[t][1] = xw[t + 12][1]; feat_s[t][2] = xw[t + 12][2];
        feat_s[t][3] = c00 * s; feat_s[t][4]  = c01 * s; feat_s[t][5]  = c02 * s;
        feat_s[t][6] = c01 * s; feat_s[t][7]  = c11 * s; feat_s[t][8]  = c12 * s;
        feat_s[t][9] = c02 * s; feat_s[t][10] = c12 * s; feat_s[t][11] = c22 * s;
    }
    __syncthreads();

    int pt = t >> 2, quarter = t & 3;     // 4 threads per point, 16 cols each
    float dv = g_dinv[point0 + pt];
    float feat[12];
    #pragma unroll
    for (int k = 0; k < 12; k++) feat[k] = feat_s[pt][k];
    #pragma unroll
    for (int jj = 0; jj < 16; jj++) {
        int j = (quarter << 4) + jj;
        float acc = bs[j];
        #pragma unroll
        for (int k = 0; k < 12; k++) acc = fmaf(feat[k], ws[k * 64 + j], acc);
        out_s[pt][j] = dv * selu_f(acc);
    }
    __syncthreads();

    for (int i = t; i < 512; i += 128) {   // 32 rows x 16 float4
        int row = i >> 4, q = i & 15;
        float4 v = *reinterpret_cast<const float4*>(&out_s[row][q << 2]);
        size_t gaddr = (size_t)(point0 + row) * 64 + (q << 2);
        *reinterpret_cast<float4*>(g_h0 + gaddr)   = v;
        *reinterpret_cast<float4*>(g_agg0 + gaddr) = v;
    }
}

// ---------------- edge scatter: agg[d] += hs[s] (vector red, nc reads) ----------------
template<int LOGG>
__global__ void edge_kernel(const int* __restrict__ src, const int* __restrict__ dst,
                            const float* __restrict__ hs, float* __restrict__ agg) {
    int idx = blockIdx.x * blockDim.x + threadIdx.x;
    int e = idx >> LOGG;
    int g = idx & ((1 << LOGG) - 1);
    if (e >= NEDGE) return;
    int s = src[e], d = dst[e];
    float4 v = ldg_nc4(reinterpret_cast<const float4*>(hs) + (((size_t)s) << LOGG) + g);
    red_add_v4(agg + ((size_t)d << (LOGG + 2)) + (g << 2), v);
}

// ---------------- single-pass TF32 GEMM, 128x128 tile, double-buffered ----------------
// out = selu( (dinv[row]*A[row]) @ W + bias ); optional fused max-pool.
// 256 threads = 8 warps (wm 0..1, wn 0..3), warp tile 64x32, mma m16n8k8.
template<int N, int K, bool DO_MAX>
__global__ void __launch_bounds__(256, 2)
gemm_tf32_kernel(const float* __restrict__ A, const float* __restrict__ dinv,
                 const float* __restrict__ Wt, const float* __restrict__ bias,
                 float* __restrict__ O1, float* __restrict__ O2,
                 float* __restrict__ lat) {
    __shared__ float Ah[2][128][20];
    __shared__ float Bh[2][16][132];

    int tid = threadIdx.x;
    int warp = tid >> 5, lane = tid & 31;
    int wm = warp >> 2, wn = warp & 3;
    int g = lane >> 2, c = lane & 3;
    int row0 = blockIdx.y * 128, col0 = blockIdx.x * 128;

    int ar = tid >> 1;                  // A row 0..127
    int ak = (tid & 1) << 3;            // 0 or 8
    float dv = dinv[row0 + ar];
    int bkr = tid >> 4;                 // B k-row 0..15
    int bc0 = (tid & 15) << 3;          // B col 0..120

    const int KT = K / 16;

    float d[4][4][4];
    #pragma unroll
    for (int mt = 0; mt < 4; mt++)
        #pragma unroll
        for (int nt = 0; nt < 4; nt++)
            #pragma unroll
            for (int r = 0; r < 4; r++) d[mt][nt][r] = 0.0f;

    // prologue: tile 0 -> buf 0
    {
        float4 a0 = *reinterpret_cast<const float4*>(A + (size_t)(row0 + ar) * K + ak);
        float4 a1 = *reinterpret_cast<const float4*>(A + (size_t)(row0 + ar) * K + ak + 4);
        Ah[0][ar][ak + 0] = f2tf32f(dv * a0.x); Ah[0][ar][ak + 1] = f2tf32f(dv * a0.y);
        Ah[0][ar][ak + 2] = f2tf32f(dv * a0.z); Ah[0][ar][ak + 3] = f2tf32f(dv * a0.w);
        Ah[0][ar][ak + 4] = f2tf32f(dv * a1.x); Ah[0][ar][ak + 5] = f2tf32f(dv * a1.y);
        Ah[0][ar][ak + 6] = f2tf32f(dv * a1.z); Ah[0][ar][ak + 7] = f2tf32f(dv * a1.w);
        float4 b0 = *reinterpret_cast<const float4*>(Wt + (size_t)bkr * N + col0 + bc0);
        float4 b1 = *reinterpret_cast<const float4*>(Wt + (size_t)bkr * N + col0 + bc0 + 4);
        Bh[0][bkr][bc0 + 0] = f2tf32f(b0.x); Bh[0][bkr][bc0 + 1] = f2tf32f(b0.y);
        Bh[0][bkr][bc0 + 2] = f2tf32f(b0.z); Bh[0][bkr][bc0 + 3] = f2tf32f(b0.w);
        Bh[0][bkr][bc0 + 4] = f2tf32f(b1.x); Bh[0][bkr][bc0 + 5] = f2tf32f(b1.y);
        Bh[0][bkr][bc0 + 6] = f2tf32f(b1.z); Bh[0][bkr][bc0 + 7] = f2tf32f(b1.w);
    }
    __syncthreads();

    for (int kt = 0; kt < KT; kt++) {
        int cur = kt & 1, nxt = cur ^ 1;
        float4 a0, a1, b0, b1;
        bool more = (kt + 1 < KT);
        if (more) {
            int koff = (kt + 1) * 16;
            a0 = *reinterpret_cast<const float4*>(A + (size_t)(row0 + ar) * K + koff + ak);
            a1 = *reinterpret_cast<const float4*>(A + (size_t)(row0 + ar) * K + koff + ak + 4);
            b0 = *reinterpret_cast<const float4*>(Wt + (size_t)(koff + bkr) * N + col0 + bc0);
            b1 = *reinterpret_cast<const float4*>(Wt + (size_t)(koff + bkr) * N + col0 + bc0 + 4);
        }

        #pragma unroll
        for (int ks = 0; ks < 2; ks++) {
            int k0 = ks << 3;
            uint32_t af[4][4];
            #pragma unroll
            for (int mt = 0; mt < 4; mt++) {
                int rm = wm * 64 + mt * 16;
                af[mt][0] = __float_as_uint(Ah[cur][rm + g][k0 + c]);
                af[mt][1] = __float_as_uint(Ah[cur][rm + g + 8][k0 + c]);
                af[mt][2] = __float_as_uint(Ah[cur][rm + g][k0 + c + 4]);
                af[mt][3] = __float_as_uint(Ah[cur][rm + g + 8][k0 + c + 4]);
            }
            uint32_t bf[4][2];
            #pragma unroll
            for (int nt = 0; nt < 4; nt++) {
                int nb = wn * 32 + nt * 8;
                bf[nt][0] = __float_as_uint(Bh[cur][k0 + c][nb + g]);
                bf[nt][1] = __float_as_uint(Bh[cur][k0 + c + 4][nb + g]);
            }
            #pragma unroll
            for (int mt = 0; mt < 4; mt++)
                #pragma unroll
                for (int nt = 0; nt < 4; nt++)
                    mma_tf32(d[mt][nt], af[mt][0], af[mt][1], af[mt][2], af[mt][3],
                             bf[nt][0], bf[nt][1]);
        }

        if (more) {
            Ah[nxt][ar][ak + 0] = f2tf32f(dv * a0.x); Ah[nxt][ar][ak + 1] = f2tf32f(dv * a0.y);
            Ah[nxt][ar][ak + 2] = f2tf32f(dv * a0.z); Ah[nxt][ar][ak + 3] = f2tf32f(dv * a0.w);
            Ah[nxt][ar][ak + 4] = f2tf32f(dv * a1.x); Ah[nxt][ar][ak + 5] = f2tf32f(dv * a1.y);
            Ah[nxt][ar][ak + 6] = f2tf32f(dv * a1.z); Ah[nxt][ar][ak + 7] = f2tf32f(dv * a1.w);
            Bh[nxt][bkr][bc0 + 0] = f2tf32f(b0.x); Bh[nxt][bkr][bc0 + 1] = f2tf32f(b0.y);
            Bh[nxt][bkr][bc0 + 2] = f2tf32f(b0.z); Bh[nxt][bkr][bc0 + 3] = f2tf32f(b0.w);
            Bh[nxt][bkr][bc0 + 4] = f2tf32f(b1.x); Bh[nxt][bkr][bc0 + 5] = f2tf32f(b1.y);
            Bh[nxt][bkr][bc0 + 6] = f2tf32f(b1.z); Bh[nxt][bkr][bc0 + 7] = f2tf32f(b1.w);
        }
        __syncthreads();
    }

    float bv[4][2];
    #pragma unroll
    for (int nt = 0; nt < 4; nt++) {
        int cc = col0 + wn * 32 + nt * 8 + (c << 1);
        bv[nt][0] = bias[cc];
        bv[nt][1] = bias[cc + 1];
    }

    if (!DO_MAX) {
        #pragma unroll
        for (int mt = 0; mt < 4; mt++) {
            int rbase = row0 + wm * 64 + mt * 16;
            #pragma unroll
            for (int half = 0; half < 2; half++) {
                int r = rbase + g + half * 8;
                float dv2 = dinv[r];
                #pragma unroll
                for (int nt = 0; nt < 4; nt++) {
                    int cc = col0 + wn * 32 + nt * 8 + (c << 1);
                    float2 o;
                    o.x = dv2 * selu_f(d[mt][nt][half * 2 + 0] + bv[nt][0]);
                    o.y = dv2 * selu_f(d[mt][nt][half * 2 + 1] + bv[nt][1]);
                    size_t addr = (size_t)r * N + cc;
                    *reinterpret_cast<float2*>(O1 + addr) = o;
                    *reinterpret_cast<float2*>(O2 + addr) = o;
                }
            }
        }
    } else {
        float mv[4][2];
        #pragma unroll
        for (int nt = 0; nt < 4; nt++) { mv[nt][0] = mv[nt][1] = __int_as_float(0xff800000); }
        #pragma unroll
        for (int mt = 0; mt < 4; mt++)
            #pragma unroll
            for (int nt = 0; nt < 4; nt++) {
                mv[nt][0] = fmaxf(mv[nt][0], fmaxf(selu_f(d[mt][nt][0] + bv[nt][0]),
                                                   selu_f(d[mt][nt][2] + bv[nt][0])));
                mv[nt][1] = fmaxf(mv[nt][1], fmaxf(selu_f(d[mt][nt][1] + bv[nt][1]),
                                                   selu_f(d[mt][nt][3] + bv[nt][1])));
            }
        #pragma unroll
        for (int off = 4; off <= 16; off <<= 1)
            #pragma unroll
            for (int nt = 0; nt < 4; nt++) {
                mv[nt][0] = fmaxf(mv[nt][0], __shfl_xor_sync(0xffffffffu, mv[nt][0], off));
                mv[nt][1] = fmaxf(mv[nt][1], __shfl_xor_sync(0xffffffffu, mv[nt][1], off));
            }
        if (lane < 4) {
            int b = row0 >> 12;
            #pragma unroll
            for (int nt = 0; nt < 4; nt++) {
                int cc = col0 + wn * 32 + nt * 8 + (lane << 1);
                atomicMaxF(&lat[b * C2 + cc], mv[nt][0]);
                atomicMaxF(&lat[b * C2 + cc + 1], mv[nt][1]);
            }
        }
    }
}

// ---------------- lat2 = selu(lat @ w_e2 + b_e2) ----------------
__global__ void e2_kernel(const float* __restrict__ lat, const float* __restrict__ w,
                          const float* __restrict__ bias, float* __restrict__ lat2) {
    __shared__ float row[C2];
    int c = threadIdx.x;
    row[c] = lat[blockIdx.x * C2 + c];
    __syncthreads();
    float acc = bias[c];
    #pragma unroll 8
    for (int k = 0; k < C2; k++) acc = fmaf(row[k], w[k * C2 + c], acc);
    lat2[blockIdx.x * C2 + c] = selu_f(acc);
}

// ---------------- decoder ----------------
__global__ void base_kernel(const float* __restrict__ lat2,
                            const float* __restrict__ w_d1,
                            const float* __restrict__ w_d2,
                            float* __restrict__ base) {
    int o = blockIdx.x;
    int b = o / 6, t = o % 6, j = t % 3;
    const float* w = (t < 3) ? w_d1 : w_d2;
    int lane = threadIdx.x;
    float s = 0.0f;
    for (int c = lane; c < C2; c += 32) s += lat2[b * C2 + c] * w[c * 3 + j];
    #pragma unroll
    for (int off = 16; off > 0; off >>= 1) s += __shfl_xor_sync(0xffffffffu, s, off);
    if (lane == 0) base[b * 6 + t] = s;
}

__global__ void final_kernel(const float* __restrict__ base,
                             const float* __restrict__ w_d1, const float* __restrict__ b_d1,
                             const float* __restrict__ w_d2, const float* __restrict__ b_d2,
                             float* __restrict__ out) {
    int idx = blockIdx.x * blockDim.x + threadIdx.x;
    int b = idx >> 12, n = idx & 4095;
    int ix = n / 46, iy = n % 46;
    float y0 = 1.0f + ix * (119.0f / 90.0f);
    float y1 = 1.0f + iy * (59.0f / 45.0f);
    float kk[3];
    #pragma unroll
    for (int j = 0; j < 3; j++)
        kk[j] = selu_f(base[b * 6 + j] + y0 * w_d1[512 * 3 + j] + y1 * w_d1[513 * 3 + j] + b_d1[j]);
    #pragma unroll
    for (int j = 0; j < 3; j++) {
        float v = base[b * 6 + 3 + j]
                + kk[0] * w_d2[512 * 3 + j]
                + kk[1] * w_d2[513 * 3 + j]
                + kk[2] * w_d2[514 * 3 + j]
                + b_d2[j];
        out[(size_t)idx * 3 + j] = selu_f(v);
    }
}

// ---------------- launch ----------------
extern "C" void kernel_launch(void* const* d_in, const int* in_sizes, int n_in,
                              void* d_out, int out_size) {
    const float* x    = (const float*)d_in[0];
    const int*   knn  = (const int*)  d_in[1];
    const float* w_e1 = (const float*)d_in[2];
    const float* b_e1 = (const float*)d_in[3];
    const float* w_g1 = (const float*)d_in[4];
    const float* b_g1 = (const float*)d_in[5];
    const float* w_g2 = (const float*)d_in[6];
    const float* b_g2 = (const float*)d_in[7];
    const float* w_e2 = (const float*)d_in[8];
    const float* b_e2 = (const float*)d_in[9];
    const float* w_d1 = (const float*)d_in[10];
    const float* b_d1 = (const float*)d_in[11];
    const float* w_d2 = (const float*)d_in[12];
    const float* b_d2 = (const float*)d_in[13];
    float* out = (float*)d_out;
    const int* src = knn;
    const int* dst = knn + NEDGE;

    float *p_h0, *p_agg0, *p_h1, *p_agg1, *p_lat, *p_lat2, *p_base, *p_dinv;
    cudaGetSymbolAddress((void**)&p_h0,   g_h0);
    cudaGetSymbolAddress((void**)&p_agg0, g_agg0);
    cudaGetSymbolAddress((void**)&p_h1,   g_h1);
    cudaGetSymbolAddress((void**)&p_agg1, g_agg1);
    cudaGetSymbolAddress((void**)&p_lat,  g_lat);
    cudaGetSymbolAddress((void**)&p_lat2, g_lat2);
    cudaGetSymbolAddress((void**)&p_base, g_base);
    cudaGetSymbolAddress((void**)&p_dinv, g_dinv);

    init_kernel<<<BN / 256, 256>>>();
    deg_kernel<<<NEDGE / 256, 256>>>(dst);
    dinv_kernel<<<BN / 256, 256>>>();
    cov_e1_kernel<<<BN / 32, 128>>>(x, w_e1, b_e1);

    // GCN layer 1
    edge_kernel<4><<<(NEDGE * 16) / 256, 256>>>(src, dst, p_h0, p_agg0);
    gemm_tf32_kernel<C1, C0, false><<<dim3(C1 / 128, BN / 128), 256>>>(
        p_agg0, p_dinv, w_g1, b_g1, p_h1, p_agg1, nullptr);

    // GCN layer 2 + fused max-pool
    edge_kernel<5><<<(NEDGE * 32) / 256, 256>>>(src, dst, p_h1, p_agg1);
    gemm_tf32_kernel<C2, C1, true><<<dim3(C2 / 128, BN / 128), 256>>>(
        p_agg1, p_dinv, w_g2, b_g2, nullptr, nullptr, p_lat);

    e2_kernel<<<NB, C2>>>(p_lat, w_e2, b_e2, p_lat2);
    base_kernel<<<NB * 6, 32>>>(p_lat2, w_d1, w_d2, p_base);
    final_kernel<<<BN / 256, 256>>>(p_base, w_d1, b_d1, w_d2, b_d2, out);
}